// round 16
// baseline (speedup 1.0000x reference)
#include <cuda_runtime.h>
#include <cstdint>

#define SEQ    4096
#define NPOS   8192
#define HEADS  16
#define DIM    64
#define DD     64
#define NCOLS_A 1024
#define ASTR   4104

__device__ float  g_abuf[(size_t)NCOLS_A * NPOS];
__device__ float2 g_Aspec[(size_t)NCOLS_A * ASTR];
__device__ float  g_xt[(size_t)128 * DIM * SEQ];

#define SW(i) ((i) ^ (((i) >> 4) & 0xF))
#define FFT_N 4096
#define FFT_SMEM_BYTES (2 * FFT_N * (int)sizeof(float2))   // ping-pong: 64 KB

// ---------- packed f32x2 helpers ----------
typedef unsigned long long u64;
__device__ __forceinline__ u64 pk2(float lo, float hi){
    u64 r; asm("mov.b64 %0, {%1, %2};" : "=l"(r) : "f"(lo), "f"(hi)); return r;
}
__device__ __forceinline__ void upk2(u64 v, float& lo, float& hi){
    asm("mov.b64 {%0, %1}, %2;" : "=f"(lo), "=f"(hi) : "l"(v));
}
__device__ __forceinline__ u64 fma2(u64 a, u64 b, u64 c){
    u64 d; asm("fma.rn.f32x2 %0, %1, %2, %3;" : "=l"(d) : "l"(a), "l"(b), "l"(c)); return d;
}
__device__ __forceinline__ u64 add2(u64 a, u64 b){
    u64 d; asm("add.rn.f32x2 %0, %1, %2;" : "=l"(d) : "l"(a), "l"(b)); return d;
}

__device__ __forceinline__ float2 cadd(float2 a, float2 b){ return make_float2(a.x+b.x, a.y+b.y); }
__device__ __forceinline__ float2 csub(float2 a, float2 b){ return make_float2(a.x-b.x, a.y-b.y); }
__device__ __forceinline__ float2 cmul(float2 a, float2 b){
    return make_float2(a.x*b.x - a.y*b.y, a.x*b.y + a.y*b.x);
}
template<int DIR>
__device__ __forceinline__ float2 mul_i(float2 z){
    return make_float2(-(float)DIR * z.y, (float)DIR * z.x);
}

template<int DIR>
__device__ __forceinline__ void dft4(float2 c0, float2 c1, float2 c2, float2 c3,
                                     float2& d0, float2& d1, float2& d2, float2& d3){
    float2 e0 = cadd(c0,c2), e1 = csub(c0,c2);
    float2 f0 = cadd(c1,c3), f1 = csub(c1,c3);
    float2 t  = mul_i<DIR>(f1);
    d0 = cadd(e0,f0); d2 = csub(e0,f0);
    d1 = cadd(e1,t);  d3 = csub(e1,t);
}

template<int DIR>
__device__ __forceinline__ void dft16_tail(float2 g[4][4], float2 a[16]){
    const float C1 = 0.92387953251128674f, S1 = 0.38268343236508978f;
    const float C2 = 0.70710678118654752f;
    const float D  = (float)DIR;
    g[1][1] = cmul(g[1][1], make_float2( C1,  D*S1));
    g[1][2] = cmul(g[1][2], make_float2( C2,  D*C2));
    g[1][3] = cmul(g[1][3], make_float2( S1,  D*C1));
    g[2][1] = cmul(g[2][1], make_float2( C2,  D*C2));
    g[2][2] = mul_i<DIR>(g[2][2]);
    g[2][3] = cmul(g[2][3], make_float2(-C2,  D*C2));
    g[3][1] = cmul(g[3][1], make_float2( S1,  D*C1));
    g[3][2] = cmul(g[3][2], make_float2(-C2,  D*C2));
    g[3][3] = cmul(g[3][3], make_float2(-C1, -D*S1));
#pragma unroll
    for (int k1 = 0; k1 < 4; k1++)
        dft4<DIR>(g[0][k1], g[1][k1], g[2][k1], g[3][k1],
                  a[k1], a[k1+4], a[k1+8], a[k1+12]);
}

template<int DIR>
__device__ __forceinline__ void dft16(float2 a[16]){
    float2 g[4][4];
#pragma unroll
    for (int n1 = 0; n1 < 4; n1++)
        dft4<DIR>(a[n1], a[n1+4], a[n1+8], a[n1+12],
                  g[n1][0], g[n1][1], g[n1][2], g[n1][3]);
    dft16_tail<DIR>(g, a);
}

template<int DIR>
__device__ __forceinline__ void dft16_half(float2 a[16]){
    float2 g[4][4];
#pragma unroll
    for (int n1 = 0; n1 < 4; n1++){
        float2 x = a[n1], y = a[n1+4];
        float2 iy = mul_i<DIR>(y);
        g[n1][0] = cadd(x, y);
        g[n1][1] = cadd(x, iy);
        g[n1][2] = csub(x, y);
        g[n1][3] = csub(x, iy);
    }
    dft16_tail<DIR>(g, a);
}

template<int DIR>
__device__ __forceinline__ void twiddle16(float2 a[16], int p, int n){
    if (p != 0){
        float ang = (float)DIR * 6.283185307179586f * (float)p / (float)n;
        float sn, cs;
        __sincosf(ang, &sn, &cs);
        float2 w1 = make_float2(cs, sn);
        float2 w2 = cmul(w1, w1);
        float2 w3 = cmul(w2, w1);
        float2 w4 = cmul(w2, w2);
        a[1] = cmul(a[1], w1); a[2] = cmul(a[2], w2); a[3] = cmul(a[3], w3);
        float2 t4 = w4;
        a[4] = cmul(a[4], t4);
        a[5] = cmul(a[5], cmul(t4, w1));
        a[6] = cmul(a[6], cmul(t4, w2));
        a[7] = cmul(a[7], cmul(t4, w3));
        float2 t8 = cmul(t4, w4);
        a[8]  = cmul(a[8],  t8);
        a[9]  = cmul(a[9],  cmul(t8, w1));
        a[10] = cmul(a[10], cmul(t8, w2));
        a[11] = cmul(a[11], cmul(t8, w3));
        float2 t12 = cmul(t8, w4);
        a[12] = cmul(a[12], t12);
        a[13] = cmul(a[13], cmul(t12, w1));
        a[14] = cmul(a[14], cmul(t12, w2));
        a[15] = cmul(a[15], cmul(t12, w3));
    }
}

template<int DIR>
__device__ __forceinline__ void fft_stage16_db(const float2* __restrict__ in,
                                               float2* __restrict__ out,
                                               int n, int s, int t){
    int p = t / s;
    int q = t - p * s;
    float2 a[16];
#pragma unroll
    for (int k = 0; k < 16; k++) a[k] = in[SW(t + 256*k)];
    dft16<DIR>(a);
    twiddle16<DIR>(a, p, n);
    int ob = q + s * 16 * p;
#pragma unroll
    for (int k = 0; k < 16; k++) out[SW(ob + s*k)] = a[k];
    __syncthreads();
}

// ------------------------- dpb MLP v5: 256 threads, 64 positions, 3 CTAs/SM -------------------------
#define POS   64
#define SACT  66
#define OFF_SW1 0
#define OFF_SW2 4096
#define OFF_SW3 8192
#define OFF_SV  9216
#define OFF_ACT 9888
#define OFF_R   (OFF_ACT + 64*SACT)
#define OFF_RED (OFF_R + 64*SACT)
#define DPB_SMEM_BYTES ((OFF_RED + 512) * 4)

// LN + relu: 4 threads per position (q = tid>>6, p = tid&63), 16 rows each.
__device__ __forceinline__ void dpb_ln(const float* __restrict__ act, float* __restrict__ r,
                                       float* __restrict__ red,
                                       const float* __restrict__ g, const float* __restrict__ be,
                                       int p, int q){
    int i0 = q * 16;
    float h[16];
    float s = 0.f;
#pragma unroll
    for (int ii = 0; ii < 16; ii++){ h[ii] = act[(i0+ii)*SACT + p]; s += h[ii]; }
    red[q*64 + p] = s;
    __syncthreads();
    float m = (red[p] + red[64+p] + red[128+p] + red[192+p]) * (1.f/64.f);
    float v = 0.f;
#pragma unroll
    for (int ii = 0; ii < 16; ii++){ float d = h[ii]-m; v += d*d; }
    red[256 + q*64 + p] = v;
    __syncthreads();
    float rs = rsqrtf((red[256+p] + red[320+p] + red[384+p] + red[448+p]) * (1.f/64.f) + 1e-5f);
#pragma unroll
    for (int ii = 0; ii < 16; ii++)
        r[(i0+ii)*SACT + p] = fmaxf((h[ii]-m)*rs*g[i0+ii] + be[i0+ii], 0.f);
}

// GEMM: aout[j][p] = bias[j] + sum_i rin[i][p]*w[i][j].
// 256 threads: tp=tid>>4 (4 positions), tj=tid&15 (4 consecutive j).
__device__ __forceinline__ void dpb_gemm(const float* __restrict__ rin, float* __restrict__ aout,
                                         const float* __restrict__ w, const float* __restrict__ bias,
                                         int tid){
    int tp = tid >> 4;
    int tj = tid & 15;
    const float* rin_b = rin + tp*4;
    const float* w_b   = w + 4*tj;
    u64 acc[2][4];
#pragma unroll
    for (int u = 0; u < 4; u++){
        float bj = bias[4*tj + u];
        u64 bp = pk2(bj, bj);
        acc[0][u] = bp; acc[1][u] = bp;
    }
#pragma unroll 8
    for (int i = 0; i < 64; i++){
        const u64* ar = reinterpret_cast<const u64*>(rin_b + i*SACT);
        u64 a0 = ar[0], a1 = ar[1];
        float4 wv = *reinterpret_cast<const float4*>(w_b + i*64);
        float ws[4] = {wv.x, wv.y, wv.z, wv.w};
#pragma unroll
        for (int u = 0; u < 4; u++){
            u64 wp = pk2(ws[u], ws[u]);
            acc[0][u] = fma2(a0, wp, acc[0][u]);
            acc[1][u] = fma2(a1, wp, acc[1][u]);
        }
    }
#pragma unroll
    for (int u = 0; u < 4; u++){
        *reinterpret_cast<u64*>(&aout[(4*tj+u)*SACT + tp*4])     = acc[0][u];
        *reinterpret_cast<u64*>(&aout[(4*tj+u)*SACT + tp*4 + 2]) = acc[1][u];
    }
}

__global__ __launch_bounds__(256, 3) void dpb_kernel(
    const float* __restrict__ w0,  const float* __restrict__ b0_,
    const float* __restrict__ g1,  const float* __restrict__ be1,
    const float* __restrict__ w1,  const float* __restrict__ b1,
    const float* __restrict__ g2,  const float* __restrict__ be2,
    const float* __restrict__ w2,  const float* __restrict__ b2,
    const float* __restrict__ g3,  const float* __restrict__ be3,
    const float* __restrict__ w3,  const float* __restrict__ b3)
{
    extern __shared__ float smf[];
    float* sw1 = smf + OFF_SW1;
    float* sw2 = smf + OFF_SW2;
    float* sw3 = smf + OFF_SW3;
    float* sv  = smf + OFF_SV;
    float* act = smf + OFF_ACT;
    float* r   = smf + OFF_R;
    float* red = smf + OFF_RED;
    int tid = threadIdx.x;

    for (int i = tid; i < 4096; i += 256){ sw1[i] = w1[i]; sw2[i] = w2[i]; }
    for (int i = tid; i < 1024; i += 256) sw3[i] = w3[i];
    if (tid < 64){
        sv[0*64+tid]=w0[tid];  sv[1*64+tid]=b0_[tid];
        sv[2*64+tid]=g1[tid];  sv[3*64+tid]=be1[tid]; sv[4*64+tid]=b1[tid];
        sv[5*64+tid]=g2[tid];  sv[6*64+tid]=be2[tid]; sv[7*64+tid]=b2[tid];
        sv[8*64+tid]=g3[tid];  sv[9*64+tid]=be3[tid];
        if (tid < HEADS) sv[10*64+tid] = b3[tid];
    }
    __syncthreads();

    // layer 0: act[i][p] = idx(p)*w0[i] + b0[i]; thread: row i = tid>>2, 16 cols
    {
        int i  = tid >> 2;
        int ph = (tid & 3) * 16;
        float w0i = sv[i], b0i = sv[64+i];
        int base = blockIdx.x * POS;
        const float scale = 1.0f / (4095.0f * 64.0f);
        for (int q2 = 0; q2 < 16; q2 += 2){
            float vals[2];
#pragma unroll
            for (int z = 0; z < 2; z++){
                int id = base + ph + q2 + z;
                int pp = id & (NPOS-1);
                int d  = id >> 13;
                float idx;
                if (pp == 0 || pp == 4096)      idx = 0.0f;
                else if (pp < 4096)             idx =  (float)((pp-1)*64 + d + 1) * scale;
                else                            idx = -(float)(4095*64 - ((pp-4097)*64 + d)) * scale;
                vals[z] = idx * w0i + b0i;
            }
            *reinterpret_cast<u64*>(&act[i*SACT + ph + q2]) = pk2(vals[0], vals[1]);
        }
    }
    __syncthreads();

    int p = tid & 63;
    int q = tid >> 6;

    dpb_ln(act, r, red, sv+2*64, sv+3*64, p, q);  __syncthreads();
    dpb_gemm(r, act, sw1, sv+4*64, tid);          __syncthreads();
    dpb_ln(act, r, red, sv+5*64, sv+6*64, p, q);  __syncthreads();
    dpb_gemm(r, act, sw2, sv+7*64, tid);          __syncthreads();

    // layer 3: LN (4-way split) + 64x16 GEMV partials, merged through r
    {
        int i0 = q * 16;
        float h[16];
        float s = 0.f;
#pragma unroll
        for (int ii = 0; ii < 16; ii++){ h[ii] = act[(i0+ii)*SACT + p]; s += h[ii]; }
        red[q*64 + p] = s;
        __syncthreads();
        float m = (red[p] + red[64+p] + red[128+p] + red[192+p]) * (1.f/64.f);
        float v = 0.f;
#pragma unroll
        for (int ii = 0; ii < 16; ii++){ float dd = h[ii]-m; v += dd*dd; }
        red[256 + q*64 + p] = v;
        __syncthreads();
        float rs = rsqrtf((red[256+p] + red[320+p] + red[384+p] + red[448+p]) * (1.f/64.f) + 1e-5f);

        u64 o[HEADS/2];
        if (q == 0){
            const u64* b3u = reinterpret_cast<const u64*>(sv + 10*64);
#pragma unroll
            for (int j = 0; j < HEADS/2; j++) o[j] = b3u[j];
        } else {
#pragma unroll
            for (int j = 0; j < HEADS/2; j++) o[j] = 0ull;
        }
#pragma unroll
        for (int ii = 0; ii < 16; ii++){
            int i = i0 + ii;
            float rr = fmaxf((h[ii]-m)*rs*sv[8*64+i] + sv[9*64+i], 0.f);
            u64 rp = pk2(rr, rr);
            const ulonglong2* wr = reinterpret_cast<const ulonglong2*>(&sw3[i*HEADS]);
#pragma unroll
            for (int jq = 0; jq < 4; jq++){
                ulonglong2 wv2 = wr[jq];
                o[2*jq]   = fma2(rp, wv2.x, o[2*jq]);
                o[2*jq+1] = fma2(rp, wv2.y, o[2*jq+1]);
            }
        }
        u64* part = reinterpret_cast<u64*>(r);
        if (q > 0){
#pragma unroll
            for (int j = 0; j < HEADS/2; j++) part[((q-1)*64 + p)*8 + j] = o[j];
        }
        __syncthreads();
        if (q == 0){
            int id = blockIdx.x*POS + p;
            int pp = id & (NPOS-1);
            int d  = id >> 13;
#pragma unroll
            for (int j = 0; j < HEADS/2; j++){
                u64 tot = add2(add2(o[j], part[p*8 + j]),
                               add2(part[(64+p)*8 + j], part[(128+p)*8 + j]));
                float lo, hi;
                upk2(tot, lo, hi);
                g_abuf[(size_t)((2*j+0)*64 + d) * NPOS + pp] = lo;
                g_abuf[(size_t)((2*j+1)*64 + d) * NPOS + pp] = hi;
            }
        }
    }
}

// ------------------------- A spectrum -------------------------
__device__ __forceinline__ void spectralA(const float2* __restrict__ Z, float2* __restrict__ Arow,
                                          int k, float2 T){
    int k2 = 4096 - k;
    float2 Zk = Z[SW(k)], Zk2 = Z[SW(k2)];
    float2 E  = make_float2((Zk.x+Zk2.x)*0.5f, (Zk.y-Zk2.y)*0.5f);
    float2 Dm = make_float2((Zk.x-Zk2.x)*0.5f, (Zk.y+Zk2.y)*0.5f);
    float2 O  = make_float2(Dm.y, -Dm.x);
    float2 TO = cmul(T, O);
    Arow[k]  = make_float2(E.x+TO.x,  E.y+TO.y);
    Arow[k2] = make_float2(E.x-TO.x, -(E.y-TO.y));
}

#define DLT make_float2(0.98078528040323044f, -0.19509032201612827f)

__global__ __launch_bounds__(256) void fft_a_kernel(){
    extern __shared__ float2 sm[];
    float2* bA = sm;
    float2* bB = sm + FFT_N;
    int t = threadIdx.x;
    int col = blockIdx.x;
    const float2* src = reinterpret_cast<const float2*>(g_abuf + (size_t)col * NPOS);
#pragma unroll
    for (int it = 0; it < 16; it++){
        int k = t + it*256;
        bA[SW(k)] = src[k];
    }
    __syncthreads();
    fft_stage16_db<-1>(bA, bB, 4096,   1, t);
    fft_stage16_db<-1>(bB, bA,  256,  16, t);
    fft_stage16_db<-1>(bA, bB,   16, 256, t);   // result in bB

    float2* Arow = g_Aspec + (size_t)col * ASTR;
    float sn, cs;
    __sincosf(-7.6699039394282068e-4f * (float)t, &sn, &cs);
    float2 T = make_float2(cs, sn);
#pragma unroll
    for (int it = 0; it < 8; it++){
        int k = t + it*256;
        if (k == 0){
            float2 Z0 = bB[SW(0)];
            Arow[0]    = make_float2(Z0.x + Z0.y, 0.f);
            Arow[4096] = make_float2(Z0.x - Z0.y, 0.f);
        } else {
            spectralA(bB, Arow, k, T);
        }
        T = cmul(T, DLT);
    }
    if (t == 0) spectralA(bB, Arow, 2048, make_float2(0.f, -1.f));
}

// ------------------------- transposes -------------------------
// split along bh so ncu's fixed -s 5 lands on dpb (launch #6) next profile
__global__ __launch_bounds__(256) void transpose_fwd(const float* __restrict__ in, int bh_base){
    __shared__ float tile[32][33];
    int d0 = blockIdx.x*32, n0 = blockIdx.y*32, bh = blockIdx.z + bh_base;
    const float* src = in + (size_t)bh * SEQ * DIM;
#pragma unroll
    for (int j = 0; j < 4; j++)
        tile[threadIdx.y + 8*j][threadIdx.x] = src[(size_t)(n0 + threadIdx.y + 8*j)*DIM + d0 + threadIdx.x];
    __syncthreads();
    float* dst = g_xt + (size_t)bh * DIM * SEQ;
#pragma unroll
    for (int j = 0; j < 4; j++)
        dst[(size_t)(d0 + threadIdx.y + 8*j)*SEQ + n0 + threadIdx.x] = tile[threadIdx.x][threadIdx.y + 8*j];
}

__global__ __launch_bounds__(256) void transpose_back(float* __restrict__ out, int bh_base){
    __shared__ float tile[32][33];
    int d0 = blockIdx.x*32, n0 = blockIdx.y*32, bh = blockIdx.z + bh_base;
    const float* src = g_xt + (size_t)bh * DIM * SEQ;
#pragma unroll
    for (int j = 0; j < 4; j++)
        tile[threadIdx.y + 8*j][threadIdx.x] = src[(size_t)(d0 + threadIdx.y + 8*j)*SEQ + n0 + threadIdx.x];
    __syncthreads();
    float* dst = out + (size_t)bh * SEQ * DIM;
#pragma unroll
    for (int j = 0; j < 4; j++)
        dst[(size_t)(n0 + threadIdx.y + 8*j)*DIM + d0 + threadIdx.x] = tile[threadIdx.x][threadIdx.y + 8*j];
}

// ------------------------- x conv -------------------------
__device__ __forceinline__ void spectralX(float2* __restrict__ Z, const float2* __restrict__ Arow,
                                          int k, float2 T){
    int k2 = 4096 - k;
    float2 Zk = Z[SW(k)], Zk2 = Z[SW(k2)];
    float2 E  = make_float2((Zk.x+Zk2.x)*0.5f, (Zk.y-Zk2.y)*0.5f);
    float2 Dm = make_float2((Zk.x-Zk2.x)*0.5f, (Zk.y+Zk2.y)*0.5f);
    float2 O  = make_float2(Dm.y, -Dm.x);
    float2 TO = cmul(T, O);
    float2 Y  = make_float2(E.x+TO.x,  E.y+TO.y);
    float2 Y2 = make_float2(E.x-TO.x, -(E.y-TO.y));
    float2 W  = cmul(Y,  Arow[k]);
    float2 W2 = cmul(Y2, Arow[k2]);
    float2 Ep = make_float2((W.x+W2.x)*0.5f, (W.y-W2.y)*0.5f);
    float2 Dp = make_float2((W.x-W2.x)*0.5f, (W.y+W2.y)*0.5f);
    float2 Op = cmul(make_float2(T.x, -T.y), Dp);
    Z[SW(k)]  = make_float2(Ep.x - Op.y,  Ep.y + Op.x);
    Z[SW(k2)] = make_float2(Ep.x + Op.y, -Ep.y + Op.x);
}

__global__ __launch_bounds__(256, 3) void fft_x_kernel(int b_base){
    extern __shared__ float2 sm[];
    float2* bA = sm;
    float2* bB = sm + FFT_N;
    int t = threadIdx.x;
    int e = blockIdx.x;          // e in [0, 4*1024)
    int b  = (e & 3) + b_base;
    int hd = e >> 2;
    int h  = hd >> 6;
    int d  = hd & 63;
    int bh = b * HEADS + h;
    float2* col = reinterpret_cast<float2*>(g_xt + ((size_t)bh * DIM + d) * SEQ);

    {
        float2 a[16];
#pragma unroll
        for (int k = 0; k < 8; k++) a[k] = col[t + 256*k];
        dft16_half<-1>(a);
        twiddle16<-1>(a, t, 4096);
#pragma unroll
        for (int k = 0; k < 16; k++) bA[SW(16*t + k)] = a[k];
    }
    __syncthreads();
    fft_stage16_db<-1>(bA, bB, 256,  16, t);
    fft_stage16_db<-1>(bB, bA,  16, 256, t);   // forward result in bA

    const float2* Arow = g_Aspec + (size_t)hd * ASTR;
    {
        float sn, cs;
        __sincosf(-7.6699039394282068e-4f * (float)t, &sn, &cs);
        float2 T = make_float2(cs, sn);
#pragma unroll
        for (int it = 0; it < 8; it++){
            int k = t + it*256;
            if (k == 0){
                float2 Z0 = bA[SW(0)];
                float Y0 = Z0.x + Z0.y;
                float Y4 = Z0.x - Z0.y;
                float W0 = Y0*Arow[0].x;
                float W4 = Y4*Arow[4096].x;
                bA[SW(0)] = make_float2((W0+W4)*0.5f, (W0-W4)*0.5f);
            } else {
                spectralX(bA, Arow, k, T);
            }
            T = cmul(T, DLT);
        }
        if (t == 0) spectralX(bA, Arow, 2048, make_float2(0.f, -1.f));
    }
    __syncthreads();

    fft_stage16_db<1>(bA, bB, 4096,  1, t);
    fft_stage16_db<1>(bB, bA,  256, 16, t);
    {
        float2 a[16];
#pragma unroll
        for (int k = 0; k < 16; k++) a[k] = bA[SW(t + 256*k)];
        dft16<1>(a);
        const float inv = 1.f / 4096.f;
#pragma unroll
        for (int k = 0; k < 8; k++)
            col[t + 256*k] = make_float2(a[k].x * inv, a[k].y * inv);
    }
}

extern "C" void kernel_launch(void* const* d_in, const int* in_sizes, int n_in,
                              void* d_out, int out_size) {
    (void)in_sizes; (void)n_in; (void)out_size;
    const float* x   = (const float*)d_in[0];
    const float* w0  = (const float*)d_in[1];
    const float* b0_ = (const float*)d_in[2];
    const float* g1  = (const float*)d_in[3];
    const float* be1 = (const float*)d_in[4];
    const float* w1  = (const float*)d_in[5];
    const float* b1  = (const float*)d_in[6];
    const float* g2  = (const float*)d_in[7];
    const float* be2 = (const float*)d_in[8];
    const float* w2  = (const float*)d_in[9];
    const float* b2  = (const float*)d_in[10];
    const float* g3  = (const float*)d_in[11];
    const float* be3 = (const float*)d_in[12];
    const float* w3  = (const float*)d_in[13];
    const float* b3  = (const float*)d_in[14];
    float* out = (float*)d_out;

    static bool init_done = false;
    static cudaStream_t s2 = nullptr;
    static cudaEvent_t evA = nullptr, evB = nullptr, evC = nullptr, evD = nullptr;
    if (!init_done) {
        cudaFuncSetAttribute(dpb_kernel,   cudaFuncAttributeMaxDynamicSharedMemorySize, DPB_SMEM_BYTES);
        cudaFuncSetAttribute(fft_a_kernel, cudaFuncAttributeMaxDynamicSharedMemorySize, FFT_SMEM_BYTES);
        cudaFuncSetAttribute(fft_x_kernel, cudaFuncAttributeMaxDynamicSharedMemorySize, FFT_SMEM_BYTES);
        cudaStreamCreateWithFlags(&s2, cudaStreamNonBlocking);
        cudaEventCreateWithFlags(&evA, cudaEventDisableTiming);
        cudaEventCreateWithFlags(&evB, cudaEventDisableTiming);
        cudaEventCreateWithFlags(&evC, cudaEventDisableTiming);
        cudaEventCreateWithFlags(&evD, cudaEventDisableTiming);
        init_done = true;
    }

    // Fork: transpose_fwd (5 chunks on s2; launches #0-4 so #5 = dpb for ncu)
    cudaEventRecord(evA, 0);
    cudaStreamWaitEvent(s2, evA, 0);
    {
        int bases[6]  = {0, 26, 52, 78, 103, 128};
        for (int c = 0; c < 5; c++){
            dim3 g(DIM/32, SEQ/32, bases[c+1]-bases[c]), t(32, 8);
            transpose_fwd<<<g, t, 0, s2>>>(x, bases[c]);
        }
    }
    cudaEventRecord(evB, s2);

    dpb_kernel<<<NPOS*DIM/POS, 256, DPB_SMEM_BYTES>>>(w0,b0_,g1,be1,w1,b1,g2,be2,w2,b2,g3,be3,w3,b3);
    fft_a_kernel<<<NCOLS_A, 256, FFT_SMEM_BYTES>>>();

    cudaStreamWaitEvent(0, evB, 0);   // join: fft_x needs g_xt + Aspec

    // Pipeline: fft_x half1 -> (t_back half1 on s2 || fft_x half2) -> t_back half2
    fft_x_kernel<<<4 * NCOLS_A, 256, FFT_SMEM_BYTES>>>(0);
    cudaEventRecord(evC, 0);
    cudaStreamWaitEvent(s2, evC, 0);
    {
        dim3 g(DIM/32, SEQ/32, 64), t(32, 8);
        transpose_back<<<g, t, 0, s2>>>(out, 0);
    }
    cudaEventRecord(evD, s2);

    fft_x_kernel<<<4 * NCOLS_A, 256, FFT_SMEM_BYTES>>>(4);
    {
        dim3 g(DIM/32, SEQ/32, 64), t(32, 8);
        transpose_back<<<g, t>>>(out, 64);
    }
    cudaStreamWaitEvent(0, evD, 0);
}

// round 17
// speedup vs baseline: 1.6242x; 1.6242x over previous
#include <cuda_runtime.h>
#include <cstdint>

#define SEQ    4096
#define NPOS   8192
#define HEADS  16
#define DIM    64
#define DD     64
#define NCOLS_A 1024
#define ASTR   4104
#define KMAX   262080          // max |k|; 16*16380
#define TROWS  16384           // node rows per side (t = k/16, 0..16380)

__device__ float  g_abuf[(size_t)NCOLS_A * NPOS];
__device__ float2 g_Aspec[(size_t)NCOLS_A * ASTR];
__device__ float  g_xt[(size_t)128 * DIM * SEQ];
__device__ float  g_tab[(size_t)2 * TROWS * HEADS];   // [side][t][h]

#define SW(i) ((i) ^ (((i) >> 4) & 0xF))
#define FFT_N 4096
#define FFT_SMEM_BYTES (2 * FFT_N * (int)sizeof(float2))

// ---------- packed f32x2 helpers ----------
typedef unsigned long long u64;
__device__ __forceinline__ u64 pk2(float lo, float hi){
    u64 r; asm("mov.b64 %0, {%1, %2};" : "=l"(r) : "f"(lo), "f"(hi)); return r;
}
__device__ __forceinline__ void upk2(u64 v, float& lo, float& hi){
    asm("mov.b64 {%0, %1}, %2;" : "=f"(lo), "=f"(hi) : "l"(v));
}
__device__ __forceinline__ u64 fma2(u64 a, u64 b, u64 c){
    u64 d; asm("fma.rn.f32x2 %0, %1, %2, %3;" : "=l"(d) : "l"(a), "l"(b), "l"(c)); return d;
}
__device__ __forceinline__ u64 add2(u64 a, u64 b){
    u64 d; asm("add.rn.f32x2 %0, %1, %2;" : "=l"(d) : "l"(a), "l"(b)); return d;
}

__device__ __forceinline__ float2 cadd(float2 a, float2 b){ return make_float2(a.x+b.x, a.y+b.y); }
__device__ __forceinline__ float2 csub(float2 a, float2 b){ return make_float2(a.x-b.x, a.y-b.y); }
__device__ __forceinline__ float2 cmul(float2 a, float2 b){
    return make_float2(a.x*b.x - a.y*b.y, a.x*b.y + a.y*b.x);
}
template<int DIR>
__device__ __forceinline__ float2 mul_i(float2 z){
    return make_float2(-(float)DIR * z.y, (float)DIR * z.x);
}

template<int DIR>
__device__ __forceinline__ void dft4(float2 c0, float2 c1, float2 c2, float2 c3,
                                     float2& d0, float2& d1, float2& d2, float2& d3){
    float2 e0 = cadd(c0,c2), e1 = csub(c0,c2);
    float2 f0 = cadd(c1,c3), f1 = csub(c1,c3);
    float2 t  = mul_i<DIR>(f1);
    d0 = cadd(e0,f0); d2 = csub(e0,f0);
    d1 = cadd(e1,t);  d3 = csub(e1,t);
}

template<int DIR>
__device__ __forceinline__ void dft16_tail(float2 g[4][4], float2 a[16]){
    const float C1 = 0.92387953251128674f, S1 = 0.38268343236508978f;
    const float C2 = 0.70710678118654752f;
    const float D  = (float)DIR;
    g[1][1] = cmul(g[1][1], make_float2( C1,  D*S1));
    g[1][2] = cmul(g[1][2], make_float2( C2,  D*C2));
    g[1][3] = cmul(g[1][3], make_float2( S1,  D*C1));
    g[2][1] = cmul(g[2][1], make_float2( C2,  D*C2));
    g[2][2] = mul_i<DIR>(g[2][2]);
    g[2][3] = cmul(g[2][3], make_float2(-C2,  D*C2));
    g[3][1] = cmul(g[3][1], make_float2( S1,  D*C1));
    g[3][2] = cmul(g[3][2], make_float2(-C2,  D*C2));
    g[3][3] = cmul(g[3][3], make_float2(-C1, -D*S1));
#pragma unroll
    for (int k1 = 0; k1 < 4; k1++)
        dft4<DIR>(g[0][k1], g[1][k1], g[2][k1], g[3][k1],
                  a[k1], a[k1+4], a[k1+8], a[k1+12]);
}

template<int DIR>
__device__ __forceinline__ void dft16(float2 a[16]){
    float2 g[4][4];
#pragma unroll
    for (int n1 = 0; n1 < 4; n1++)
        dft4<DIR>(a[n1], a[n1+4], a[n1+8], a[n1+12],
                  g[n1][0], g[n1][1], g[n1][2], g[n1][3]);
    dft16_tail<DIR>(g, a);
}

template<int DIR>
__device__ __forceinline__ void dft16_half(float2 a[16]){
    float2 g[4][4];
#pragma unroll
    for (int n1 = 0; n1 < 4; n1++){
        float2 x = a[n1], y = a[n1+4];
        float2 iy = mul_i<DIR>(y);
        g[n1][0] = cadd(x, y);
        g[n1][1] = cadd(x, iy);
        g[n1][2] = csub(x, y);
        g[n1][3] = csub(x, iy);
    }
    dft16_tail<DIR>(g, a);
}

template<int DIR>
__device__ __forceinline__ void twiddle16(float2 a[16], int p, int n){
    if (p != 0){
        float ang = (float)DIR * 6.283185307179586f * (float)p / (float)n;
        float sn, cs;
        __sincosf(ang, &sn, &cs);
        float2 w1 = make_float2(cs, sn);
        float2 w2 = cmul(w1, w1);
        float2 w3 = cmul(w2, w1);
        float2 w4 = cmul(w2, w2);
        a[1] = cmul(a[1], w1); a[2] = cmul(a[2], w2); a[3] = cmul(a[3], w3);
        float2 t4 = w4;
        a[4] = cmul(a[4], t4);
        a[5] = cmul(a[5], cmul(t4, w1));
        a[6] = cmul(a[6], cmul(t4, w2));
        a[7] = cmul(a[7], cmul(t4, w3));
        float2 t8 = cmul(t4, w4);
        a[8]  = cmul(a[8],  t8);
        a[9]  = cmul(a[9],  cmul(t8, w1));
        a[10] = cmul(a[10], cmul(t8, w2));
        a[11] = cmul(a[11], cmul(t8, w3));
        float2 t12 = cmul(t8, w4);
        a[12] = cmul(a[12], t12);
        a[13] = cmul(a[13], cmul(t12, w1));
        a[14] = cmul(a[14], cmul(t12, w2));
        a[15] = cmul(a[15], cmul(t12, w3));
    }
}

template<int DIR>
__device__ __forceinline__ void fft_stage16_db(const float2* __restrict__ in,
                                               float2* __restrict__ out,
                                               int n, int s, int t){
    int p = t / s;
    int q = t - p * s;
    float2 a[16];
#pragma unroll
    for (int k = 0; k < 16; k++) a[k] = in[SW(t + 256*k)];
    dft16<DIR>(a);
    twiddle16<DIR>(a, p, n);
    int ob = q + s * 16 * p;
#pragma unroll
    for (int k = 0; k < 16; k++) out[SW(ob + s*k)] = a[k];
    __syncthreads();
}

// ------------------------- dpb_eval: MLP at 32768 node slots -------------------------
#define SACT 130
#define OFF_SW1 0
#define OFF_SW2 4096
#define OFF_SW3 8192
#define OFF_SV  9216
#define OFF_ACT 9872
#define OFF_R   (OFF_ACT + 64*SACT)
#define OFF_RED (OFF_R + 64*SACT)
#define DPB_SMEM_BYTES ((OFF_RED + 512) * 4)

__device__ __forceinline__ void dpb_ln(const float* __restrict__ act, float* __restrict__ r,
                                       float* __restrict__ red,
                                       const float* __restrict__ g, const float* __restrict__ be,
                                       int p, int half){
    int i0 = half * 32;
    float h[32];
    float s = 0.f;
#pragma unroll
    for (int ii = 0; ii < 32; ii++){ h[ii] = act[(i0+ii)*SACT + p]; s += h[ii]; }
    red[half*128 + p] = s;
    __syncthreads();
    float m = (red[p] + red[128+p]) * (1.f/64.f);
    float v = 0.f;
#pragma unroll
    for (int ii = 0; ii < 32; ii++){ float d = h[ii]-m; v += d*d; }
    red[256 + half*128 + p] = v;
    __syncthreads();
    float rs = rsqrtf((red[256+p] + red[384+p]) * (1.f/64.f) + 1e-5f);
#pragma unroll
    for (int ii = 0; ii < 32; ii++)
        r[(i0+ii)*SACT + p] = fmaxf((h[ii]-m)*rs*g[i0+ii] + be[i0+ii], 0.f);
}

__device__ __forceinline__ void dpb_gemm(const float* __restrict__ rin, float* __restrict__ aout,
                                         const float* __restrict__ w, const float* __restrict__ bias,
                                         int tid){
    int tp = tid >> 4;
    int tj = tid & 15;
    const float* rin_b = rin + tp*8;
    const float* w_b   = w + 4*tj;
    u64 acc[4][4];
#pragma unroll
    for (int u = 0; u < 4; u++){
        float bj = bias[4*tj + u];
        u64 bp = pk2(bj, bj);
#pragma unroll
        for (int u2 = 0; u2 < 4; u2++) acc[u2][u] = bp;
    }
#pragma unroll 8
    for (int i = 0; i < 64; i++){
        u64 a2[4];
        const u64* ar = reinterpret_cast<const u64*>(rin_b + i*SACT);
#pragma unroll
        for (int u2 = 0; u2 < 4; u2++) a2[u2] = ar[u2];
        float4 wv = *reinterpret_cast<const float4*>(w_b + i*64);
        float ws[4] = {wv.x, wv.y, wv.z, wv.w};
#pragma unroll
        for (int u = 0; u < 4; u++){
            u64 wp = pk2(ws[u], ws[u]);
#pragma unroll
            for (int u2 = 0; u2 < 4; u2++) acc[u2][u] = fma2(a2[u2], wp, acc[u2][u]);
        }
    }
#pragma unroll
    for (int u = 0; u < 4; u++)
#pragma unroll
        for (int u2 = 0; u2 < 4; u2++)
            *reinterpret_cast<u64*>(&aout[(4*tj+u)*SACT + tp*8 + 2*u2]) = acc[u2][u];
}

// slot id = side*16384 + t : idx = (side? -1:+1) * (16*min(t,16380)) * scale
__global__ __launch_bounds__(256) void dpb_eval(
    const float* __restrict__ w0,  const float* __restrict__ b0_,
    const float* __restrict__ g1,  const float* __restrict__ be1,
    const float* __restrict__ w1,  const float* __restrict__ b1,
    const float* __restrict__ g2,  const float* __restrict__ be2,
    const float* __restrict__ w2,  const float* __restrict__ b2,
    const float* __restrict__ g3,  const float* __restrict__ be3,
    const float* __restrict__ w3,  const float* __restrict__ b3)
{
    extern __shared__ float smf[];
    float* sw1 = smf + OFF_SW1;
    float* sw2 = smf + OFF_SW2;
    float* sw3 = smf + OFF_SW3;
    float* sv  = smf + OFF_SV;
    float* act = smf + OFF_ACT;
    float* r   = smf + OFF_R;
    float* red = smf + OFF_RED;
    int tid = threadIdx.x;

    for (int i = tid; i < 4096; i += 256){ sw1[i] = w1[i]; sw2[i] = w2[i]; }
    for (int i = tid; i < 1024; i += 256) sw3[i] = w3[i];
    if (tid < 64){
        sv[0*64+tid]=w0[tid];  sv[1*64+tid]=b0_[tid];
        sv[2*64+tid]=g1[tid];  sv[3*64+tid]=be1[tid]; sv[4*64+tid]=b1[tid];
        sv[5*64+tid]=g2[tid];  sv[6*64+tid]=be2[tid]; sv[7*64+tid]=b2[tid];
        sv[8*64+tid]=g3[tid];  sv[9*64+tid]=be3[tid];
        if (tid < HEADS) sv[10*64+tid] = b3[tid];
    }
    __syncthreads();

    // layer 0: act[i][slot] = idx(slot)*w0[i] + b0[i]
    {
        int i  = tid >> 2;
        int ph = (tid & 3) * 32;
        float w0i = sv[i], b0i = sv[64+i];
        int base = blockIdx.x * 128;
        const float scale = 1.0f / (4095.0f * 64.0f);
        for (int q = 0; q < 32; q += 2){
            float vals[2];
#pragma unroll
            for (int z = 0; z < 2; z++){
                int id = base + ph + q + z;
                int side = id >> 14;
                int t = id & (TROWS-1);
                if (t > 16380) t = 16380;
                float idx = (float)(16*t) * scale;
                if (side) idx = -idx;
                vals[z] = idx * w0i + b0i;
            }
            *reinterpret_cast<u64*>(&act[i*SACT + ph + q]) = pk2(vals[0], vals[1]);
        }
    }
    __syncthreads();

    int p    = tid & 127;
    int half = tid >> 7;

    dpb_ln(act, r, red, sv+2*64, sv+3*64, p, half);  __syncthreads();
    dpb_gemm(r, act, sw1, sv+4*64, tid);             __syncthreads();
    dpb_ln(act, r, red, sv+5*64, sv+6*64, p, half);  __syncthreads();
    dpb_gemm(r, act, sw2, sv+7*64, tid);             __syncthreads();

    // layer 3: LN (split) + 64x16 GEMV partials, merged through r; store node row
    {
        int i0 = half * 32;
        float h[32];
        float s = 0.f;
#pragma unroll
        for (int ii = 0; ii < 32; ii++){ h[ii] = act[(i0+ii)*SACT + p]; s += h[ii]; }
        red[half*128 + p] = s;
        __syncthreads();
        float m = (red[p] + red[128+p]) * (1.f/64.f);
        float v = 0.f;
#pragma unroll
        for (int ii = 0; ii < 32; ii++){ float dd = h[ii]-m; v += dd*dd; }
        red[256 + half*128 + p] = v;
        __syncthreads();
        float rs = rsqrtf((red[256+p] + red[384+p]) * (1.f/64.f) + 1e-5f);

        u64 o[HEADS/2];
        if (half == 0){
            const u64* b3u = reinterpret_cast<const u64*>(sv + 10*64);
#pragma unroll
            for (int j = 0; j < HEADS/2; j++) o[j] = b3u[j];
        } else {
#pragma unroll
            for (int j = 0; j < HEADS/2; j++) o[j] = 0ull;
        }
#pragma unroll
        for (int ii = 0; ii < 32; ii++){
            int i = i0 + ii;
            float rr = fmaxf((h[ii]-m)*rs*sv[8*64+i] + sv[9*64+i], 0.f);
            u64 rp = pk2(rr, rr);
            const ulonglong2* wr = reinterpret_cast<const ulonglong2*>(&sw3[i*HEADS]);
#pragma unroll
            for (int jq = 0; jq < 4; jq++){
                ulonglong2 wv2 = wr[jq];
                o[2*jq]   = fma2(rp, wv2.x, o[2*jq]);
                o[2*jq+1] = fma2(rp, wv2.y, o[2*jq+1]);
            }
        }
        u64* part = reinterpret_cast<u64*>(r);
        if (half == 1){
#pragma unroll
            for (int j = 0; j < HEADS/2; j++) part[p*8 + j] = o[j];
        }
        __syncthreads();
        if (half == 0){
            int slot = blockIdx.x*128 + p;
            u64* row = reinterpret_cast<u64*>(g_tab + (size_t)slot * HEADS);
#pragma unroll
            for (int j = 0; j < HEADS/2; j++)
                row[j] = add2(o[j], part[p*8 + j]);
        }
    }
}

// ------------------------- dpb_interp: table -> g_abuf -------------------------
__global__ __launch_bounds__(256) void dpb_interp(){
    int id = blockIdx.x * 256 + threadIdx.x;   // id = d*8192 + p
    int p = id & (NPOS-1);
    int d = id >> 13;
    int k, side;
    if (p == 0 || p == 4096){ k = 0; side = 0; }
    else if (p < 4096){ k = (p-1)*64 + d + 1; side = 0; }
    else { k = KMAX - (p-4097)*64 - d; side = 1; }
    int t0 = k >> 4;
    int fr = k & 15;
    int t1 = t0 + (fr ? 1 : 0);
    float f = (float)fr * (1.f/16.f);
    const float* A = g_tab + ((size_t)(side*TROWS + t0)) * HEADS;
    const float* B = g_tab + ((size_t)(side*TROWS + t1)) * HEADS;
    float o[HEADS];
#pragma unroll
    for (int h = 0; h < HEADS; h++){
        float a = A[h];
        o[h] = a + f * (B[h] - a);
    }
#pragma unroll
    for (int h = 0; h < HEADS; h++)
        g_abuf[(size_t)(h*64 + d) * NPOS + p] = o[h];
}

// ------------------------- A spectrum -------------------------
__device__ __forceinline__ void spectralA(const float2* __restrict__ Z, float2* __restrict__ Arow,
                                          int k, float2 T){
    int k2 = 4096 - k;
    float2 Zk = Z[SW(k)], Zk2 = Z[SW(k2)];
    float2 E  = make_float2((Zk.x+Zk2.x)*0.5f, (Zk.y-Zk2.y)*0.5f);
    float2 Dm = make_float2((Zk.x-Zk2.x)*0.5f, (Zk.y+Zk2.y)*0.5f);
    float2 O  = make_float2(Dm.y, -Dm.x);
    float2 TO = cmul(T, O);
    Arow[k]  = make_float2(E.x+TO.x,  E.y+TO.y);
    Arow[k2] = make_float2(E.x-TO.x, -(E.y-TO.y));
}

#define DLT make_float2(0.98078528040323044f, -0.19509032201612827f)

__global__ __launch_bounds__(256) void fft_a_kernel(){
    extern __shared__ float2 sm[];
    float2* bA = sm;
    float2* bB = sm + FFT_N;
    int t = threadIdx.x;
    int col = blockIdx.x;
    const float2* src = reinterpret_cast<const float2*>(g_abuf + (size_t)col * NPOS);
#pragma unroll
    for (int it = 0; it < 16; it++){
        int k = t + it*256;
        bA[SW(k)] = src[k];
    }
    __syncthreads();
    fft_stage16_db<-1>(bA, bB, 4096,   1, t);
    fft_stage16_db<-1>(bB, bA,  256,  16, t);
    fft_stage16_db<-1>(bA, bB,   16, 256, t);   // result in bB

    float2* Arow = g_Aspec + (size_t)col * ASTR;
    float sn, cs;
    __sincosf(-7.6699039394282068e-4f * (float)t, &sn, &cs);
    float2 T = make_float2(cs, sn);
#pragma unroll
    for (int it = 0; it < 8; it++){
        int k = t + it*256;
        if (k == 0){
            float2 Z0 = bB[SW(0)];
            Arow[0]    = make_float2(Z0.x + Z0.y, 0.f);
            Arow[4096] = make_float2(Z0.x - Z0.y, 0.f);
        } else {
            spectralA(bB, Arow, k, T);
        }
        T = cmul(T, DLT);
    }
    if (t == 0) spectralA(bB, Arow, 2048, make_float2(0.f, -1.f));
}

// ------------------------- transposes -------------------------
__global__ __launch_bounds__(256) void transpose_fwd(const float* __restrict__ in){
    __shared__ float tile[32][33];
    int d0 = blockIdx.x*32, n0 = blockIdx.y*32, bh = blockIdx.z;
    const float* src = in + (size_t)bh * SEQ * DIM;
#pragma unroll
    for (int j = 0; j < 4; j++)
        tile[threadIdx.y + 8*j][threadIdx.x] = src[(size_t)(n0 + threadIdx.y + 8*j)*DIM + d0 + threadIdx.x];
    __syncthreads();
    float* dst = g_xt + (size_t)bh * DIM * SEQ;
#pragma unroll
    for (int j = 0; j < 4; j++)
        dst[(size_t)(d0 + threadIdx.y + 8*j)*SEQ + n0 + threadIdx.x] = tile[threadIdx.x][threadIdx.y + 8*j];
}

__global__ __launch_bounds__(256) void transpose_back(float* __restrict__ out, int bh_base){
    __shared__ float tile[32][33];
    int d0 = blockIdx.x*32, n0 = blockIdx.y*32, bh = blockIdx.z + bh_base;
    const float* src = g_xt + (size_t)bh * DIM * SEQ;
#pragma unroll
    for (int j = 0; j < 4; j++)
        tile[threadIdx.y + 8*j][threadIdx.x] = src[(size_t)(d0 + threadIdx.y + 8*j)*SEQ + n0 + threadIdx.x];
    __syncthreads();
    float* dst = out + (size_t)bh * SEQ * DIM;
#pragma unroll
    for (int j = 0; j < 4; j++)
        dst[(size_t)(n0 + threadIdx.y + 8*j)*DIM + d0 + threadIdx.x] = tile[threadIdx.x][threadIdx.y + 8*j];
}

// ------------------------- x conv -------------------------
__device__ __forceinline__ void spectralX(float2* __restrict__ Z, const float2* __restrict__ Arow,
                                          int k, float2 T){
    int k2 = 4096 - k;
    float2 Zk = Z[SW(k)], Zk2 = Z[SW(k2)];
    float2 E  = make_float2((Zk.x+Zk2.x)*0.5f, (Zk.y-Zk2.y)*0.5f);
    float2 Dm = make_float2((Zk.x-Zk2.x)*0.5f, (Zk.y+Zk2.y)*0.5f);
    float2 O  = make_float2(Dm.y, -Dm.x);
    float2 TO = cmul(T, O);
    float2 Y  = make_float2(E.x+TO.x,  E.y+TO.y);
    float2 Y2 = make_float2(E.x-TO.x, -(E.y-TO.y));
    float2 W  = cmul(Y,  Arow[k]);
    float2 W2 = cmul(Y2, Arow[k2]);
    float2 Ep = make_float2((W.x+W2.x)*0.5f, (W.y-W2.y)*0.5f);
    float2 Dp = make_float2((W.x-W2.x)*0.5f, (W.y+W2.y)*0.5f);
    float2 Op = cmul(make_float2(T.x, -T.y), Dp);
    Z[SW(k)]  = make_float2(Ep.x - Op.y,  Ep.y + Op.x);
    Z[SW(k2)] = make_float2(Ep.x + Op.y, -Ep.y + Op.x);
}

__global__ __launch_bounds__(256, 3) void fft_x_kernel(int b_base){
    extern __shared__ float2 sm[];
    float2* bA = sm;
    float2* bB = sm + FFT_N;
    int t = threadIdx.x;
    int e = blockIdx.x;
    int b  = (e & 3) + b_base;
    int hd = e >> 2;
    int h  = hd >> 6;
    int d  = hd & 63;
    int bh = b * HEADS + h;
    float2* col = reinterpret_cast<float2*>(g_xt + ((size_t)bh * DIM + d) * SEQ);

    {
        float2 a[16];
#pragma unroll
        for (int k = 0; k < 8; k++) a[k] = col[t + 256*k];
        dft16_half<-1>(a);
        twiddle16<-1>(a, t, 4096);
#pragma unroll
        for (int k = 0; k < 16; k++) bA[SW(16*t + k)] = a[k];
    }
    __syncthreads();
    fft_stage16_db<-1>(bA, bB, 256,  16, t);
    fft_stage16_db<-1>(bB, bA,  16, 256, t);   // forward result in bA

    const float2* Arow = g_Aspec + (size_t)hd * ASTR;
    {
        float sn, cs;
        __sincosf(-7.6699039394282068e-4f * (float)t, &sn, &cs);
        float2 T = make_float2(cs, sn);
#pragma unroll
        for (int it = 0; it < 8; it++){
            int k = t + it*256;
            if (k == 0){
                float2 Z0 = bA[SW(0)];
                float Y0 = Z0.x + Z0.y;
                float Y4 = Z0.x - Z0.y;
                float W0 = Y0*Arow[0].x;
                float W4 = Y4*Arow[4096].x;
                bA[SW(0)] = make_float2((W0+W4)*0.5f, (W0-W4)*0.5f);
            } else {
                spectralX(bA, Arow, k, T);
            }
            T = cmul(T, DLT);
        }
        if (t == 0) spectralX(bA, Arow, 2048, make_float2(0.f, -1.f));
    }
    __syncthreads();

    fft_stage16_db<1>(bA, bB, 4096,  1, t);
    fft_stage16_db<1>(bB, bA,  256, 16, t);
    {
        float2 a[16];
#pragma unroll
        for (int k = 0; k < 16; k++) a[k] = bA[SW(t + 256*k)];
        dft16<1>(a);
        const float inv = 1.f / 4096.f;
#pragma unroll
        for (int k = 0; k < 8; k++)
            col[t + 256*k] = make_float2(a[k].x * inv, a[k].y * inv);
    }
}

extern "C" void kernel_launch(void* const* d_in, const int* in_sizes, int n_in,
                              void* d_out, int out_size) {
    (void)in_sizes; (void)n_in; (void)out_size;
    const float* x   = (const float*)d_in[0];
    const float* w0  = (const float*)d_in[1];
    const float* b0_ = (const float*)d_in[2];
    const float* g1  = (const float*)d_in[3];
    const float* be1 = (const float*)d_in[4];
    const float* w1  = (const float*)d_in[5];
    const float* b1  = (const float*)d_in[6];
    const float* g2  = (const float*)d_in[7];
    const float* be2 = (const float*)d_in[8];
    const float* w2  = (const float*)d_in[9];
    const float* b2  = (const float*)d_in[10];
    const float* g3  = (const float*)d_in[11];
    const float* be3 = (const float*)d_in[12];
    const float* w3  = (const float*)d_in[13];
    const float* b3  = (const float*)d_in[14];
    float* out = (float*)d_out;

    static bool init_done = false;
    static cudaStream_t s2 = nullptr;
    static cudaEvent_t evA = nullptr, evB = nullptr, evC = nullptr, evD = nullptr;
    if (!init_done) {
        cudaFuncSetAttribute(dpb_eval,     cudaFuncAttributeMaxDynamicSharedMemorySize, DPB_SMEM_BYTES);
        cudaFuncSetAttribute(fft_a_kernel, cudaFuncAttributeMaxDynamicSharedMemorySize, FFT_SMEM_BYTES);
        cudaFuncSetAttribute(fft_x_kernel, cudaFuncAttributeMaxDynamicSharedMemorySize, FFT_SMEM_BYTES);
        cudaStreamCreateWithFlags(&s2, cudaStreamNonBlocking);
        cudaEventCreateWithFlags(&evA, cudaEventDisableTiming);
        cudaEventCreateWithFlags(&evB, cudaEventDisableTiming);
        cudaEventCreateWithFlags(&evC, cudaEventDisableTiming);
        cudaEventCreateWithFlags(&evD, cudaEventDisableTiming);
        init_done = true;
    }

    // Fork: transpose_fwd overlaps dpb_eval + dpb_interp + fft_a.
    cudaEventRecord(evA, 0);
    cudaStreamWaitEvent(s2, evA, 0);
    {
        dim3 g(DIM/32, SEQ/32, 128), t(32, 8);
        transpose_fwd<<<g, t, 0, s2>>>(x);
    }
    cudaEventRecord(evB, s2);

    // 1. MLP at 32768 nodes  2. interpolate to all 524288 positions
    dpb_eval<<<(2*TROWS)/128, 256, DPB_SMEM_BYTES>>>(w0,b0_,g1,be1,w1,b1,g2,be2,w2,b2,g3,be3,w3,b3);
    dpb_interp<<<(NPOS*DIM)/256, 256>>>();
    fft_a_kernel<<<NCOLS_A, 256, FFT_SMEM_BYTES>>>();

    cudaStreamWaitEvent(0, evB, 0);   // join: fft_x needs g_xt + Aspec

    // Pipeline: fft_x half1 -> (t_back half1 on s2 || fft_x half2) -> t_back half2
    fft_x_kernel<<<4 * NCOLS_A, 256, FFT_SMEM_BYTES>>>(0);
    cudaEventRecord(evC, 0);
    cudaStreamWaitEvent(s2, evC, 0);
    {
        dim3 g(DIM/32, SEQ/32, 64), t(32, 8);
        transpose_back<<<g, t, 0, s2>>>(out, 0);
    }
    cudaEventRecord(evD, s2);

    fft_x_kernel<<<4 * NCOLS_A, 256, FFT_SMEM_BYTES>>>(4);
    {
        dim3 g(DIM/32, SEQ/32, 64), t(32, 8);
        transpose_back<<<g, t>>>(out, 64);
    }
    cudaStreamWaitEvent(0, evD, 0);
}